// round 2
// baseline (speedup 1.0000x reference)
#include <cuda_runtime.h>
#include <cuda_bf16.h>

#define N_NODES 100000
#define N_EDGES 1600000
#define IN_F 256
#define OUT_F 64
#define ALPHA 0.2f

// Scratch (no allocations allowed in kernel_launch)
__device__ __align__(16) float g_h[N_NODES * OUT_F];
__device__ float g_s1[N_NODES];
__device__ float g_s2[N_NODES];
__device__ float g_denom[N_NODES];
__device__ float g_ex[N_EDGES];

// ---------------------------------------------------------------------------
// init: zero output accumulator and denom
// ---------------------------------------------------------------------------
__global__ void init_kernel(float* __restrict__ out) {
    int i = blockIdx.x * blockDim.x + threadIdx.x;
    int stride = gridDim.x * blockDim.x;
    for (int j = i; j < N_NODES * OUT_F; j += stride) out[j] = 0.0f;
    for (int j = i; j < N_NODES; j += stride) g_denom[j] = 0.0f;
}

// ---------------------------------------------------------------------------
// GEMM: h[100000,64] = x[100000,256] @ W[256,64]
// Block: 256 threads (16x16), tile 64 rows x 64 cols, 4x4 micro-tile, K chunks of 16.
// ---------------------------------------------------------------------------
__global__ void gemm_kernel(const float* __restrict__ x,
                            const float* __restrict__ W) {
    __shared__ float xs[64][20];  // +4 pad to dodge bank conflicts
    __shared__ float ws[16][64];

    int tid = threadIdx.x;
    int tx = tid & 15;       // output column group
    int ty = tid >> 4;       // output row group
    int row0 = blockIdx.x * 64;

    float acc[4][4];
#pragma unroll
    for (int i = 0; i < 4; i++)
#pragma unroll
        for (int j = 0; j < 4; j++) acc[i][j] = 0.0f;

    for (int kc = 0; kc < IN_F; kc += 16) {
        // load x tile: 64 rows x 16 k, one float4 per thread
        {
            int r = tid >> 2;
            int seg = (tid & 3) << 2;
            int grow = row0 + r;
            float4 v = make_float4(0.f, 0.f, 0.f, 0.f);
            if (grow < N_NODES)
                v = *(const float4*)&x[(long long)grow * IN_F + kc + seg];
            xs[r][seg + 0] = v.x;
            xs[r][seg + 1] = v.y;
            xs[r][seg + 2] = v.z;
            xs[r][seg + 3] = v.w;
        }
        // load W tile: 16 k x 64 cols, one float4 per thread
        {
            int kk = tid >> 4;
            int c = (tid & 15) << 2;
            float4 v = *(const float4*)&W[(kc + kk) * OUT_F + c];
            *(float4*)&ws[kk][c] = v;
        }
        __syncthreads();

#pragma unroll
        for (int kk = 0; kk < 16; kk++) {
            float a0 = xs[ty * 4 + 0][kk];
            float a1 = xs[ty * 4 + 1][kk];
            float a2 = xs[ty * 4 + 2][kk];
            float a3 = xs[ty * 4 + 3][kk];
            float4 b = *(float4*)&ws[kk][tx * 4];
            acc[0][0] += a0 * b.x; acc[0][1] += a0 * b.y; acc[0][2] += a0 * b.z; acc[0][3] += a0 * b.w;
            acc[1][0] += a1 * b.x; acc[1][1] += a1 * b.y; acc[1][2] += a1 * b.z; acc[1][3] += a1 * b.w;
            acc[2][0] += a2 * b.x; acc[2][1] += a2 * b.y; acc[2][2] += a2 * b.z; acc[2][3] += a2 * b.w;
            acc[3][0] += a3 * b.x; acc[3][1] += a3 * b.y; acc[3][2] += a3 * b.z; acc[3][3] += a3 * b.w;
        }
        __syncthreads();
    }

#pragma unroll
    for (int i = 0; i < 4; i++) {
        int r = row0 + ty * 4 + i;
        if (r < N_NODES) {
            float4 v = make_float4(acc[i][0], acc[i][1], acc[i][2], acc[i][3]);
            *(float4*)&g_h[(long long)r * OUT_F + tx * 4] = v;
        }
    }
}

// ---------------------------------------------------------------------------
// s1/s2: per-node dot products h[n]·a1, h[n]·a2. One warp per node.
// ---------------------------------------------------------------------------
__global__ void s_kernel(const float* __restrict__ a) {
    int gwarp = (blockIdx.x * blockDim.x + threadIdx.x) >> 5;
    int lane = threadIdx.x & 31;
    if (gwarp >= N_NODES) return;
    float v0 = g_h[gwarp * OUT_F + lane];
    float v1 = g_h[gwarp * OUT_F + 32 + lane];
    float p1 = v0 * a[lane] + v1 * a[32 + lane];
    float p2 = v0 * a[64 + lane] + v1 * a[96 + lane];
#pragma unroll
    for (int o = 16; o; o >>= 1) {
        p1 += __shfl_xor_sync(0xFFFFFFFFu, p1, o);
        p2 += __shfl_xor_sync(0xFFFFFFFFu, p2, o);
    }
    if (lane == 0) {
        g_s1[gwarp] = p1;
        g_s2[gwarp] = p2;
    }
}

// ---------------------------------------------------------------------------
// edge pass 1: ex = exp(leakyrelu(s1[src]+s2[dst])); denom[src] += ex
// Skipping segment-max: logits are O(10), exp is fp32-safe, and the softmax
// ratio is mathematically identical with or without the max shift.
// ---------------------------------------------------------------------------
__global__ void edge1_kernel(const int* __restrict__ idx) {
    int e = blockIdx.x * blockDim.x + threadIdx.x;
    if (e >= N_EDGES) return;
    int src = idx[e];
    int dst = idx[N_EDGES + e];
    float l = g_s1[src] + g_s2[dst];
    float lv = l > 0.0f ? l : ALPHA * l;
    float ex = __expf(lv);
    g_ex[e] = ex;
    atomicAdd(&g_denom[src], ex);
}

// ---------------------------------------------------------------------------
// edge pass 2: out[src] += (ex/denom[src]) * h[dst]
// 16 lanes per edge, float4 gather + red.global.add.v4.f32 scatter.
// ---------------------------------------------------------------------------
__global__ void edge2_kernel(const int* __restrict__ idx,
                             float* __restrict__ out) {
    long long gt = (long long)blockIdx.x * blockDim.x + threadIdx.x;
    int e = (int)(gt >> 4);
    int lane = (int)(gt & 15);
    if (e >= N_EDGES) return;
    int src = idx[e];
    int dst = idx[N_EDGES + e];
    float att = g_ex[e] / g_denom[src];
    float4 v = *(const float4*)&g_h[(long long)dst * OUT_F + lane * 4];
    float* op = out + (long long)src * OUT_F + lane * 4;
    asm volatile(
        "red.global.add.v4.f32 [%0], {%1, %2, %3, %4};"
        :: "l"(op), "f"(att * v.x), "f"(att * v.y), "f"(att * v.z), "f"(att * v.w)
        : "memory");
}

// ---------------------------------------------------------------------------
// elu epilogue (in place on out)
// ---------------------------------------------------------------------------
__global__ void elu_kernel(float* __restrict__ out) {
    int i = blockIdx.x * blockDim.x + threadIdx.x;
    if (i < N_NODES * OUT_F) {
        float v = out[i];
        out[i] = v > 0.0f ? v : expm1f(v);
    }
}

// ---------------------------------------------------------------------------
extern "C" void kernel_launch(void* const* d_in, const int* in_sizes, int n_in,
                              void* d_out, int out_size) {
    const float* x = (const float*)d_in[0];
    const int* idx = (const int*)d_in[1];
    const float* W = (const float*)d_in[2];
    const float* a = (const float*)d_in[3];
    float* out = (float*)d_out;

    init_kernel<<<2048, 256>>>(out);
    gemm_kernel<<<(N_NODES + 63) / 64, 256>>>(x, W);
    s_kernel<<<(N_NODES + 7) / 8, 256>>>(a);
    edge1_kernel<<<(N_EDGES + 255) / 256, 256>>>(idx);
    edge2_kernel<<<(N_EDGES * 16 + 255) / 256, 256>>>(idx, out);
    elu_kernel<<<(N_NODES * OUT_F + 255) / 256, 256>>>(out);
}